// round 7
// baseline (speedup 1.0000x reference)
#include <cuda_runtime.h>

// Problem dims (fixed by the reference)
#define Bn  4
#define Qn  256
#define KVn 1024
#define Hn  128
#define VSn 256

// Scratch: Eq = e^{2*clamp(q_proj)}, Ek = e^{2*clamp(k_proj)}
__device__ float g_Eq[Bn * Qn * Hn];    // [B*Q, H]
__device__ float g_Ek[Bn * KVn * Hn];   // [B*KV, H]

// 2*log2(e): e^{2x} = 2^{x * 2*log2(e)}
#define TWO_LOG2E 2.885390081777927f

// ---------------------------------------------------------------------------
// Kernel 1: project rows and emit E = exp2(clamp(proj, +-40) * 2*log2(e)).
// Each block handles 8 rows; thread t owns output column t.
// ---------------------------------------------------------------------------
__global__ void proj_kernel(const float* __restrict__ queries,
                            const float* __restrict__ keys,
                            const float* __restrict__ Wq,
                            const float* __restrict__ Wk) {
    const int r0 = blockIdx.x * 8;
    const float* in;
    const float* W;
    float* outp;
    if (r0 < Bn * Qn) {
        in   = queries + r0 * Hn;
        W    = Wq;
        outp = g_Eq + r0 * Hn;
    } else {
        const int rr = r0 - Bn * Qn;
        in   = keys + rr * Hn;
        W    = Wk;
        outp = g_Ek + rr * Hn;
    }
    __shared__ float s[8][Hn];
    const int t = threadIdx.x;
    #pragma unroll
    for (int rr = 0; rr < 8; rr++) s[rr][t] = in[rr * Hn + t];
    __syncthreads();

    float a[8];
    #pragma unroll
    for (int rr = 0; rr < 8; rr++) a[rr] = 0.f;

    #pragma unroll 4
    for (int kk = 0; kk < Hn; kk++) {
        const float w = W[kk * Hn + t];
        #pragma unroll
        for (int rr = 0; rr < 8; rr++)
            a[rr] = fmaf(s[rr][kk], w, a[rr]);
    }
    #pragma unroll
    for (int rr = 0; rr < 8; rr++) {
        float p = fminf(fmaxf(a[rr], -40.f), 40.f) * TWO_LOG2E;
        float e;
        asm("ex2.approx.f32 %0, %1;" : "=f"(e) : "f"(p));
        outp[rr * Hn + t] = e;
    }
}

// ---------------------------------------------------------------------------
// Kernel 2: one block per (b, query-pair). 256 threads (8 warps). R=2 rows.
//
// Pass 1 (scores): 8-lane-per-key geometry, 4 keys/warp, BOTH queries per
//   key load. Per h: d=fma(Eq,Ek,1); r=rcp(d); s=fma(-2w,r,s).
//   tanh(x) = 1 - 2/(e^{2x}+1); Sum_h w_h hoisted into the accumulator init.
//   3-level shfl_xor reduces all 4 keys x 2 queries simultaneously.
// Pass 2: block softmax per query, matching the -1e6 masking semantics;
//         valid_len == 0 degenerates to uniform weights over all KV.
// Pass 3: thread-per-output-column AV; each V element feeds both queries.
// ---------------------------------------------------------------------------
__global__ void attn_kernel(const float* __restrict__ values,
                            const int* __restrict__ valid_lens,
                            const float* __restrict__ wv,
                            float* __restrict__ out) {
    const int blk  = blockIdx.x;            // [0, 512)
    const int b    = blk & 3;               // batch-interleaved for balance
    const int qp   = blk >> 2;              // query pair index [0,128)
    const int row0 = (b << 8) + qp * 2;     // b*256 + 2*qp
    const int row1 = row0 + 1;
    const int tid  = threadIdx.x;
    const int lane = tid & 31;
    const int warp = tid >> 5;

    __shared__ float s_sc[2][KVn];
    __shared__ float s_red[2][8];

    const int L     = valid_lens[b];
    const bool uni  = (L <= 0);        // all slots masked -> uniform softmax
    const int effL  = uni ? KVn : L;

    float Z0, Z1;
    if (!uni) {
        // ---- Pass 1: scores for both query rows ----
        const int sub = lane >> 3;          // which key of the quad (0..3)
        const int hb  = (lane & 7) << 4;    // h-chunk base (16 floats)

        float4 qa[4], qb[4], w2[4];
        float wsum_l = 0.f;
        #pragma unroll
        for (int i = 0; i < 4; i++) {
            qa[i] = *reinterpret_cast<const float4*>(&g_Eq[row0 * Hn + hb + i * 4]);
            qb[i] = *reinterpret_cast<const float4*>(&g_Eq[row1 * Hn + hb + i * 4]);
            float4 w = *reinterpret_cast<const float4*>(&wv[hb + i * 4]);
            wsum_l += ((w.x + w.y) + (w.z + w.w));
            w2[i] = make_float4(-2.f * w.x, -2.f * w.y, -2.f * w.z, -2.f * w.w);
        }
        const float* kb = g_Ek + b * KVn * Hn;

        for (int j0 = warp * 4; j0 < effL; j0 += 32) {
            const int key = j0 + sub;
            const int kc  = (key < effL) ? key : (effL - 1);  // clamp (safe load)

            float4 k4[4];
            #pragma unroll
            for (int i = 0; i < 4; i++)
                k4[i] = *reinterpret_cast<const float4*>(&kb[kc * Hn + hb + i * 4]);

            // 32 independent rcp chains (16 per query), 2 accum chains each
            float sa0 = wsum_l, sb0 = 0.f, sa1 = wsum_l, sb1 = 0.f;
            #pragma unroll
            for (int i = 0; i < 4; i++) {
                float r0, r1, r2, r3, u0, u1, u2, u3;
                asm("rcp.approx.f32 %0, %1;" : "=f"(r0) : "f"(fmaf(qa[i].x, k4[i].x, 1.f)));
                asm("rcp.approx.f32 %0, %1;" : "=f"(r1) : "f"(fmaf(qa[i].y, k4[i].y, 1.f)));
                asm("rcp.approx.f32 %0, %1;" : "=f"(r2) : "f"(fmaf(qa[i].z, k4[i].z, 1.f)));
                asm("rcp.approx.f32 %0, %1;" : "=f"(r3) : "f"(fmaf(qa[i].w, k4[i].w, 1.f)));
                asm("rcp.approx.f32 %0, %1;" : "=f"(u0) : "f"(fmaf(qb[i].x, k4[i].x, 1.f)));
                asm("rcp.approx.f32 %0, %1;" : "=f"(u1) : "f"(fmaf(qb[i].y, k4[i].y, 1.f)));
                asm("rcp.approx.f32 %0, %1;" : "=f"(u2) : "f"(fmaf(qb[i].z, k4[i].z, 1.f)));
                asm("rcp.approx.f32 %0, %1;" : "=f"(u3) : "f"(fmaf(qb[i].w, k4[i].w, 1.f)));
                sa0 = fmaf(w2[i].x, r0, sa0);
                sb0 = fmaf(w2[i].y, r1, sb0);
                sa0 = fmaf(w2[i].z, r2, sa0);
                sb0 = fmaf(w2[i].w, r3, sb0);
                sa1 = fmaf(w2[i].x, u0, sa1);
                sb1 = fmaf(w2[i].y, u1, sb1);
                sa1 = fmaf(w2[i].z, u2, sa1);
                sb1 = fmaf(w2[i].w, u3, sb1);
            }
            float s0 = sa0 + sb0;
            float s1 = sa1 + sb1;

            // reduce across the 8 lanes of each key group
            s0 += __shfl_xor_sync(0xffffffffu, s0, 1);
            s1 += __shfl_xor_sync(0xffffffffu, s1, 1);
            s0 += __shfl_xor_sync(0xffffffffu, s0, 2);
            s1 += __shfl_xor_sync(0xffffffffu, s1, 2);
            s0 += __shfl_xor_sync(0xffffffffu, s0, 4);
            s1 += __shfl_xor_sync(0xffffffffu, s1, 4);

            if ((lane & 7) == 0 && key < effL) {
                s_sc[0][key] = s0;
                s_sc[1][key] = s1;
            }
        }
        __syncthreads();

        // ---- Pass 2: softmax (max, exp, sum) for each query row ----
        float Zr[2];
        #pragma unroll
        for (int r = 0; r < 2; r++) {
            float m = -3.0e38f;
            for (int jj = tid; jj < effL; jj += 256) m = fmaxf(m, s_sc[r][jj]);
            #pragma unroll
            for (int o = 16; o > 0; o >>= 1)
                m = fmaxf(m, __shfl_xor_sync(0xffffffffu, m, o));
            if (lane == 0) s_red[r][warp] = m;
        }
        __syncthreads();
        #pragma unroll
        for (int r = 0; r < 2; r++) {
            float M = s_red[r][0];
            #pragma unroll
            for (int k = 1; k < 8; k++) M = fmaxf(M, s_red[r][k]);

            float z = 0.f;
            for (int jj = tid; jj < effL; jj += 256) {
                const float e = __expf(s_sc[r][jj] - M);
                s_sc[r][jj] = e;
                z += e;
            }
            #pragma unroll
            for (int o = 16; o > 0; o >>= 1)
                z += __shfl_xor_sync(0xffffffffu, z, o);
            Zr[r] = z;   // full only on lane 0 pattern; finalize below
            if (lane == 0) s_red[r][warp] = z;
        }
        __syncthreads();
        Z0 = s_red[0][0]; Z1 = s_red[1][0];
        #pragma unroll
        for (int k = 1; k < 8; k++) {
            Z0 += s_red[0][k];
            Z1 += s_red[1][k];
        }
        (void)Zr;
    } else {
        // valid_len == 0: reference gives softmax over all -1e6 -> uniform
        for (int jj = tid; jj < KVn; jj += 256) {
            s_sc[0][jj] = 1.0f;
            s_sc[1][jj] = 1.0f;
        }
        __syncthreads();
        Z0 = (float)KVn;
        Z1 = (float)KVn;
    }

    // ---- Pass 3: AV. Thread tid owns column tid; V reused for both rows ----
    const int c = tid;
    const float* vb = values + (size_t)b * KVn * VSn + c;
    float a0[4], a1[4];
    #pragma unroll
    for (int u = 0; u < 4; u++) { a0[u] = 0.f; a1[u] = 0.f; }

    int j = 0;
    for (; j + 4 <= effL; j += 4) {
        #pragma unroll
        for (int u = 0; u < 4; u++) {
            const float v = vb[(j + u) * VSn];
            a0[u] = fmaf(s_sc[0][j + u], v, a0[u]);
            a1[u] = fmaf(s_sc[1][j + u], v, a1[u]);
        }
    }
    for (; j < effL; j++) {
        const float v = vb[j * VSn];
        a0[0] = fmaf(s_sc[0][j], v, a0[0]);
        a1[0] = fmaf(s_sc[1][j], v, a1[0]);
    }

    out[row0 * VSn + c] = ((a0[0] + a0[1]) + (a0[2] + a0[3])) / Z0;
    out[row1 * VSn + c] = ((a1[0] + a1[1]) + (a1[2] + a1[3])) / Z1;
}

// ---------------------------------------------------------------------------
extern "C" void kernel_launch(void* const* d_in, const int* in_sizes, int n_in,
                              void* d_out, int out_size) {
    const float* queries = (const float*)d_in[0];
    const float* keys    = (const float*)d_in[1];
    const float* values  = (const float*)d_in[2];
    const int*   valid   = (const int*)d_in[3];
    const float* Wq      = (const float*)d_in[4];
    const float* Wk      = (const float*)d_in[5];
    const float* wv      = (const float*)d_in[6];
    float* out           = (float*)d_out;

    proj_kernel<<<(Bn * Qn + Bn * KVn) / 8, 128>>>(queries, keys, Wq, Wk);
    attn_kernel<<<(Bn * Qn) / 2, 256>>>(values, valid, wv, out);
}